// round 13
// baseline (speedup 1.0000x reference)
#include <cuda_runtime.h>
#include <cstdint>
#include <math.h>

// ---------------------------------------------------------------------------
// EmbeddingLSTMCell on GB300 (sm_103a) -- base-target mma.sync path
//   z = [x | h_prev] @ [Wf|Wi|Wc|Wo] + b    (B=8192, K=4096, 4*HID=8192)
//   f,i,o = sigmoid; c~ = tanh; c_t = c_prev*f + i*c~; h_t = o*tanh(c_t)
//
// R12: ldmatrix operand staging. Prep pass rounds x/h to tf32 grid AND
// transposes W -> Wt[n][k] (rounded). Both A and B smem tiles are then
// [row][32k] with 36-float pitch, and fragments load via
// ldmatrix.m8n8.x4.b16 whose thread mapping equals the tf32 m16n8k8
// fragment layout (A row-major, B n-major). 128 LDS -> 32 LDSM per
// warp-stage. Bit-identical numerics to R11.
// ---------------------------------------------------------------------------

#define THREADS      128
#define BM           128
#define BK           32
#define NKT          128          // 4096 / 32
#define STAGES       3
#define ROW_F        36           // 32 + 4 pad floats (144B pitch, LDSM clean)
#define TILE_BYTES   (128 * ROW_F * 4)               // 18432
#define B_OFF        TILE_BYTES
#define STAGE_BYTES  (2 * TILE_BYTES)                // 36864
#define SMEM_TOTAL   (STAGES * STAGE_BYTES)          // 110592 (x2 CTAs < 228K)
#define ZS           132          // zbuf row stride; 128*132*4 = 67584 B

#define NF_X   16777216           // 8192*2048
#define NF_W   8388608            // 4096*2048 per gate

// pre-rounded operands; Wt is [gate][n=2048][k=4096] (transposed, rounded)
__device__ float g_xr[NF_X];
__device__ float g_hr[NF_X];
__device__ float g_wtr[4 * NF_W];

static __device__ __forceinline__ uint32_t smem_u32(const void* p) {
    uint32_t a;
    asm("{ .reg .u64 t; cvta.to.shared.u64 t, %1; cvt.u32.u64 %0, t; }"
        : "=r"(a) : "l"(p));
    return a;
}

static __device__ __forceinline__ uint32_t f2tf(float f) {
    uint32_t r;
    asm("cvt.rna.tf32.f32 %0, %1;" : "=r"(r) : "f"(f));
    return r;
}

static __device__ __forceinline__ void cp16(uint32_t saddr, const void* g) {
    asm volatile("cp.async.cg.shared.global [%0], [%1], 16;"
                 :: "r"(saddr), "l"(g));
}

static __device__ __forceinline__ void ldsm4(uint32_t* d, uint32_t addr) {
    asm volatile(
        "ldmatrix.sync.aligned.m8n8.x4.shared.b16 {%0,%1,%2,%3}, [%4];"
        : "=r"(d[0]), "=r"(d[1]), "=r"(d[2]), "=r"(d[3]) : "r"(addr));
}

static __device__ __forceinline__ void mma8(float* c, const uint32_t* a,
                                            const uint32_t* b) {
    asm volatile(
        "mma.sync.aligned.m16n8k8.row.col.f32.tf32.tf32.f32 "
        "{%0,%1,%2,%3}, {%4,%5,%6,%7}, {%8,%9}, {%0,%1,%2,%3};"
        : "+f"(c[0]), "+f"(c[1]), "+f"(c[2]), "+f"(c[3])
        : "r"(a[0]), "r"(a[1]), "r"(a[2]), "r"(a[3]), "r"(b[0]), "r"(b[1]));
}

// ---- prep 1: round x / h_prev to tf32 grid ----
__global__ void __launch_bounds__(256)
round_kernel(const float* __restrict__ x, const float* __restrict__ hp)
{
    const int t = blockIdx.x * blockDim.x + threadIdx.x;
    const int stride = gridDim.x * blockDim.x;
    const float4* s4 = (const float4*)(blockIdx.y ? hp : x);
    uint4* d4 = (uint4*)(blockIdx.y ? g_hr : g_xr);
    for (int i = t; i < NF_X / 4; i += stride) {
        float4 v = s4[i];
        uint4 u;
        u.x = f2tf(v.x); u.y = f2tf(v.y); u.z = f2tf(v.z); u.w = f2tf(v.w);
        d4[i] = u;
    }
}

// ---- prep 2: transpose + round W[k][n] -> Wt[n][k], per gate ----
__global__ void __launch_bounds__(256)
transpose_kernel(const float* __restrict__ Wf, const float* __restrict__ Wi,
                 const float* __restrict__ Wc, const float* __restrict__ Wo)
{
    __shared__ float tile[32][33];
    const int g  = blockIdx.z;
    const float* W = (g == 0) ? Wf : (g == 1) ? Wi : (g == 2) ? Wc : Wo;
    const int n0 = blockIdx.x * 32;      // 64 tiles over n=2048
    const int k0 = blockIdx.y * 32;      // 128 tiles over k=4096
    const int tx = threadIdx.x & 31;
    const int ty = threadIdx.x >> 5;     // 0..7
    #pragma unroll
    for (int i = 0; i < 4; i++) {
        const int k = ty * 4 + i;
        tile[k][tx] = __uint_as_float(
            f2tf(W[(size_t)(k0 + k) * 2048 + n0 + tx]));
    }
    __syncthreads();
    float* dst = g_wtr + (size_t)g * NF_W;
    #pragma unroll
    for (int i = 0; i < 4; i++) {
        const int n = ty * 4 + i;
        dst[(size_t)(n0 + n) * 4096 + k0 + tx] = tile[tx][n];
    }
}

__global__ void __launch_bounds__(THREADS, 2)
lstm_fused_kernel(const float* __restrict__ cp,
                  const float* __restrict__ bf, const float* __restrict__ bi,
                  const float* __restrict__ bc, const float* __restrict__ bo,
                  float* __restrict__ out)
{
    extern __shared__ char smem[];
    const int tid  = threadIdx.x;
    const int lane = tid & 31;
    const int wid  = tid >> 5;     // 0..3
    const int wm   = wid & 1;      // warp row (M): 2 warps * 64 rows
    const int wn   = wid >> 1;     // warp col (N): 2 warps * 64 cols
    const int tr   = lane >> 2;    // groupID (0..7)
    const int tc   = lane & 3;     // thread-in-group (0..3)
    const int nt   = blockIdx.x;   // 0..63 hid tile (32 hid cols per gate)
    const int mt   = blockIdx.y;   // 0..63 batch tile (128 rows)
    const uint32_t sbase = smem_u32(smem);

    float acc[4][8][4];
    #pragma unroll
    for (int mi = 0; mi < 4; mi++)
        #pragma unroll
        for (int ni = 0; ni < 8; ni++)
            #pragma unroll
            for (int j = 0; j < 4; j++) acc[mi][ni][j] = 0.0f;

    // ---- async stage fill: A and B both [128 rows][32 k], 144B pitch ----
    auto fill = [&](int kt, int s) {
        const uint32_t sb = sbase + (uint32_t)s * STAGE_BYTES;
        const float* asrc = (kt < 64) ? g_xr : g_hr;
        const int kb = (kt & 63) * BK;
        #pragma unroll
        for (int i = 0; i < 8; i++) {
            const int q = tid + i * THREADS;    // 0..1023
            const int r = q >> 3, c = q & 7;
            cp16(sb + r * (ROW_F * 4) + c * 16,
                 asrc + (size_t)(mt * BM + r) * 2048 + kb + c * 4);
        }
        // B rows: row = g*32 + j -> Wt global n-row g*2048 + nt*32 + j
        #pragma unroll
        for (int i = 0; i < 8; i++) {
            const int q = tid + i * THREADS;    // 0..1023
            const int r = q >> 3, c = q & 7;
            const int nrow = ((r >> 5) << 11) + nt * 32 + (r & 31);
            cp16(sb + B_OFF + r * (ROW_F * 4) + c * 16,
                 g_wtr + (size_t)nrow * 4096 + kt * BK + c * 4);
        }
    };

    // ---- per-lane LDSM base addressing (matrix q = lane>>3, row lane&7) ----
    const int mq = lane >> 3, mr = lane & 7;
    // A frag mi: matrices (rows +{0,8}, k +{0,4}) in order a0,a1,a2,a3
    const uint32_t aoff = ((wm * 64 + (mq & 1) * 8 + mr) * ROW_F
                           + (mq >> 1) * 4) * 4;
    // B frag pair (2np,2np+1): matrices (n +{0,8} x k +{0,4}) order
    //   b[2np][0], b[2np][1], b[2np+1][0], b[2np+1][1]
    const uint32_t boff = (uint32_t)B_OFF
                        + ((wn * 64 + (mq >> 1) * 8 + mr) * ROW_F
                           + (mq & 1) * 4) * 4;

    // ---- compute one K-stage: 8 LDSM.x4 + 32 HMMA per k8 step ----
    auto compute = [&](int s) {
        const uint32_t sb = sbase + (uint32_t)s * STAGE_BYTES;
        #pragma unroll
        for (int ks = 0; ks < 4; ks++) {
            uint32_t a[4][4], b[4][4];
            #pragma unroll
            for (int mi = 0; mi < 4; mi++)
                ldsm4(a[mi], sb + aoff + mi * 16 * ROW_F * 4 + ks * 32);
            #pragma unroll
            for (int np = 0; np < 4; np++)
                ldsm4(b[np], sb + boff + np * 16 * ROW_F * 4 + ks * 32);
            #pragma unroll
            for (int mi = 0; mi < 4; mi++)
                #pragma unroll
                for (int np = 0; np < 4; np++) {
                    mma8(acc[mi][2 * np],     a[mi], &b[np][0]);
                    mma8(acc[mi][2 * np + 1], a[mi], &b[np][2]);
                }
        }
    };

    // ---- 3-stage cp.async pipeline (2 prefetched) ----
    fill(0, 0); asm volatile("cp.async.commit_group;" ::: "memory");
    fill(1, 1); asm volatile("cp.async.commit_group;" ::: "memory");

    int cs = 0, fs = 2;
    for (int kt = 0; kt < NKT; kt++) {
        if (kt < NKT - 1) asm volatile("cp.async.wait_group 1;" ::: "memory");
        else              asm volatile("cp.async.wait_group 0;" ::: "memory");
        __syncthreads();
        if (kt + 2 < NKT) {
            fill(kt + 2, fs);
            asm volatile("cp.async.commit_group;" ::: "memory");
            fs = (fs == STAGES - 1) ? 0 : fs + 1;
        }
        compute(cs);
        cs = (cs == STAGES - 1) ? 0 : cs + 1;
    }

    // ---- epilogue: acc -> smem zbuf -> fused LSTM math -> h_t, c_t ----
    __syncthreads();
    float* z = (float*)smem;
    #pragma unroll
    for (int mi = 0; mi < 4; mi++)
        #pragma unroll
        for (int ni = 0; ni < 8; ni++) {
            const int r0  = wm * 64 + mi * 16 + tr;
            const int col = wn * 64 + ni * 8 + tc * 2;
            z[r0 * ZS + col]           = acc[mi][ni][0];
            z[r0 * ZS + col + 1]       = acc[mi][ni][1];
            z[(r0 + 8) * ZS + col]     = acc[mi][ni][2];
            z[(r0 + 8) * ZS + col + 1] = acc[mi][ni][3];
        }
    __syncthreads();

    const int j   = tid & 31;
    const int rw  = tid >> 5;           // 0..3
    const int hid = nt * 32 + j;
    const float bfv = bf[hid], biv = bi[hid], bcv = bc[hid], bov = bo[hid];
    float* out_h = out;
    float* out_c = out + (size_t)8192 * 2048;

    #pragma unroll 4
    for (int p = 0; p < 32; p++) {
        const int row = p * 4 + rw;
        const float zf = z[row * ZS + j]      + bfv;
        const float zi = z[row * ZS + 32 + j] + biv;
        const float zc = z[row * ZS + 64 + j] + bcv;
        const float zo = z[row * ZS + 96 + j] + bov;
        const size_t gi = (size_t)(mt * BM + row) * 2048 + hid;
        const float cprev = cp[gi];
        const float ft = 1.0f / (1.0f + __expf(-zf));
        const float it = 1.0f / (1.0f + __expf(-zi));
        const float cb = tanhf(zc);
        const float ot = 1.0f / (1.0f + __expf(-zo));
        const float ct = cprev * ft + it * cb;
        out_h[gi] = ot * tanhf(ct);
        out_c[gi] = ct;
    }
}

extern "C" void kernel_launch(void* const* d_in, const int* in_sizes, int n_in,
                              void* d_out, int out_size) {
    (void)in_sizes; (void)n_in; (void)out_size;
    const float* x  = (const float*)d_in[0];
    const float* hp = (const float*)d_in[1];
    const float* cp = (const float*)d_in[2];
    // d_in[3] = embedding_vec (ignored in vanilla mode)
    const float* Wf = (const float*)d_in[4];
    const float* Wi = (const float*)d_in[5];
    const float* Wc = (const float*)d_in[6];
    const float* Wo = (const float*)d_in[7];
    const float* bf = (const float*)d_in[8];
    const float* bi = (const float*)d_in[9];
    const float* bc = (const float*)d_in[10];
    const float* bo = (const float*)d_in[11];
    float* out = (float*)d_out;

    // 1) pre-round x/h; transpose+round W -> Wt[n][k]
    dim3 rgrid(1024, 2);
    round_kernel<<<rgrid, 256>>>(x, hp);
    dim3 tgrid(64, 128, 4);
    transpose_kernel<<<tgrid, 256>>>(Wf, Wi, Wc, Wo);

    // 2) fused GEMM + LSTM epilogue
    cudaFuncSetAttribute(lstm_fused_kernel,
                         cudaFuncAttributeMaxDynamicSharedMemorySize, SMEM_TOTAL);
    dim3 grid(64, 64);   // x = nt (fastest), y = mt
    lstm_fused_kernel<<<grid, THREADS, SMEM_TOTAL>>>(
        cp, bf, bi, bc, bo, out);
}

// round 14
// speedup vs baseline: 1.4861x; 1.4861x over previous
#include <cuda_runtime.h>
#include <cstdint>
#include <math.h>

// ---------------------------------------------------------------------------
// EmbeddingLSTMCell on GB300 (sm_103a) -- base-target mma.sync path
//   z = [x | h_prev] @ [Wf|Wi|Wc|Wo] + b    (B=8192, K=4096, 4*HID=8192)
//   f,i,o = sigmoid; c~ = tanh; c_t = c_prev*f + i*c~; h_t = o*tanh(c_t)
//
// R14: occupancy attack. Revert R12's ldmatrix/transpose (regressed).
// R11 layout + pipeline, but 256 threads/CTA, 8 warps as 2m x 4n with
// warp tile 64x32 (acc 64 regs) and __launch_bounds__(256,2):
// 2 CTAs/SM -> 4 warps/SMSP (was 2) to cover LDS->MMA latency.
// Operands pre-rounded to tf32 grid (no CVT in loop), 3-stage cp.async.
// ---------------------------------------------------------------------------

#define THREADS      256
#define BM           128
#define BK           32
#define NKT          128          // 4096 / 32
#define STAGES       3
#define A_ROW_F      36           // 32 + 4 pad (A frag banks 4*tr+tc distinct)
#define B_ROW_F      136          // 128 + 8 pad (B frag banks 8*tc+tr distinct)
#define A_BYTES      (BM * A_ROW_F * 4)              // 18432
#define B_OFF        A_BYTES
#define STAGE_BYTES  (A_BYTES + 32 * B_ROW_F * 4)    // 35840
#define SMEM_TOTAL   (STAGES * STAGE_BYTES)          // 107520 (x2 CTAs = 215K)
#define ZS           132          // zbuf row stride; 128*132*4 = 67584 B

#define NF_X   16777216           // 8192*2048
#define NF_W   8388608            // 4096*2048
#define N4_X   (NF_X / 4)
#define N4_W   (NF_W / 4)

// pre-rounded (rna->tf32, stored as fp32 with low 13 bits zero) operands
__device__ float g_xr[NF_X];
__device__ float g_hr[NF_X];
__device__ float g_wfr[NF_W];
__device__ float g_wir[NF_W];
__device__ float g_wcr[NF_W];
__device__ float g_wor[NF_W];

static __device__ __forceinline__ uint32_t smem_u32(const void* p) {
    uint32_t a;
    asm("{ .reg .u64 t; cvta.to.shared.u64 t, %1; cvt.u32.u64 %0, t; }"
        : "=r"(a) : "l"(p));
    return a;
}

static __device__ __forceinline__ uint32_t f2tf(float f) {
    uint32_t r;
    asm("cvt.rna.tf32.f32 %0, %1;" : "=r"(r) : "f"(f));
    return r;
}

static __device__ __forceinline__ void cp16(uint32_t saddr, const void* g) {
    asm volatile("cp.async.cg.shared.global [%0], [%1], 16;"
                 :: "r"(saddr), "l"(g));
}

static __device__ __forceinline__ void mma8(float* c, const uint32_t* a,
                                            const uint32_t* b) {
    asm volatile(
        "mma.sync.aligned.m16n8k8.row.col.f32.tf32.tf32.f32 "
        "{%0,%1,%2,%3}, {%4,%5,%6,%7}, {%8,%9}, {%0,%1,%2,%3};"
        : "+f"(c[0]), "+f"(c[1]), "+f"(c[2]), "+f"(c[3])
        : "r"(a[0]), "r"(a[1]), "r"(a[2]), "r"(a[3]), "r"(b[0]), "r"(b[1]));
}

// ---- prep: rna-round to tf32 grid, store bit patterns as fp32 ----
__global__ void __launch_bounds__(256)
prep_kernel(const float* __restrict__ x,  const float* __restrict__ hp,
            const float* __restrict__ Wf, const float* __restrict__ Wi,
            const float* __restrict__ Wc, const float* __restrict__ Wo)
{
    const int t = blockIdx.x * blockDim.x + threadIdx.x;
    const int stride = gridDim.x * blockDim.x;
    const float* src; float* dst; int n4;
    switch (blockIdx.y) {
        case 0:  src = x;  dst = g_xr;  n4 = N4_X; break;
        case 1:  src = hp; dst = g_hr;  n4 = N4_X; break;
        case 2:  src = Wf; dst = g_wfr; n4 = N4_W; break;
        case 3:  src = Wi; dst = g_wir; n4 = N4_W; break;
        case 4:  src = Wc; dst = g_wcr; n4 = N4_W; break;
        default: src = Wo; dst = g_wor; n4 = N4_W; break;
    }
    const float4* s4 = (const float4*)src;
    uint4* d4 = (uint4*)dst;
    for (int i = t; i < n4; i += stride) {
        float4 v = s4[i];
        uint4 u;
        u.x = f2tf(v.x); u.y = f2tf(v.y); u.z = f2tf(v.z); u.w = f2tf(v.w);
        d4[i] = u;
    }
}

__global__ void __launch_bounds__(THREADS, 2)
lstm_fused_kernel(const float* __restrict__ cp,
                  const float* __restrict__ bf, const float* __restrict__ bi,
                  const float* __restrict__ bc, const float* __restrict__ bo,
                  float* __restrict__ out)
{
    extern __shared__ char smem[];
    const int tid  = threadIdx.x;
    const int lane = tid & 31;
    const int wid  = tid >> 5;     // 0..7
    const int wm   = wid & 1;      // warp row (M): 2 warps * 64 rows
    const int wn   = wid >> 1;     // warp col (N): 4 warps * 32 cols
    const int tr   = lane >> 2;    // groupID (0..7)
    const int tc   = lane & 3;     // thread-in-group (0..3)
    const int nt   = blockIdx.x;   // 0..63 hid tile (32 hid cols per gate)
    const int mt   = blockIdx.y;   // 0..63 batch tile (128 rows)
    const uint32_t sbase = smem_u32(smem);

    float acc[4][4][4];
    #pragma unroll
    for (int mi = 0; mi < 4; mi++)
        #pragma unroll
        for (int ni = 0; ni < 4; ni++)
            #pragma unroll
            for (int j = 0; j < 4; j++) acc[mi][ni][j] = 0.0f;

    // ---- async stage fill: 2048 16B chunks per stage, 8 per thread ----
    auto fill = [&](int kt, int s) {
        const uint32_t sb = sbase + (uint32_t)s * STAGE_BYTES;
        const float* asrc = (kt < 64) ? g_xr : g_hr;
        const int kb = (kt & 63) * BK;
        #pragma unroll
        for (int i = 0; i < 4; i++) {
            const int q = tid + i * THREADS;    // 0..1023
            const int r = q >> 3, c = q & 7;
            cp16(sb + r * (A_ROW_F * 4) + c * 16,
                 asrc + (size_t)(mt * BM + r) * 2048 + kb + c * 4);
        }
        #pragma unroll
        for (int i = 0; i < 4; i++) {
            const int q = tid + i * THREADS;    // 0..1023
            const int k = q >> 5, ch = q & 31;
            const int g = ch >> 3, j = (ch & 7) * 4;
            const float* w = (g == 0) ? g_wfr : (g == 1) ? g_wir
                           : (g == 2) ? g_wcr : g_wor;
            cp16(sb + B_OFF + k * (B_ROW_F * 4) + g * 128 + j * 4,
                 w + (size_t)(kt * BK + k) * 2048 + nt * 32 + j);
        }
    };

    // ---- compute one K-stage: 4 k8 steps x (4 m-frags x 4 n-frags) ----
    auto compute = [&](int s) {
        const char* st = smem + (size_t)s * STAGE_BYTES;
        const float* As = (const float*)st;
        const float* Bs = (const float*)(st + B_OFF);
        #pragma unroll
        for (int ks = 0; ks < 4; ks++) {
            uint32_t a[4][4], b[4][2];
            #pragma unroll
            for (int mi = 0; mi < 4; mi++) {
                const float* ap = As + (wm * 64 + mi * 16 + tr) * A_ROW_F
                                     + ks * 8 + tc;
                a[mi][0] = __float_as_uint(ap[0]);
                a[mi][1] = __float_as_uint(ap[8 * A_ROW_F]);
                a[mi][2] = __float_as_uint(ap[4]);
                a[mi][3] = __float_as_uint(ap[8 * A_ROW_F + 4]);
            }
            #pragma unroll
            for (int ni = 0; ni < 4; ni++) {
                const float* bp = Bs + (ks * 8 + tc) * B_ROW_F
                                     + wn * 32 + ni * 8 + tr;
                b[ni][0] = __float_as_uint(bp[0]);
                b[ni][1] = __float_as_uint(bp[4 * B_ROW_F]);
            }
            #pragma unroll
            for (int mi = 0; mi < 4; mi++)
                #pragma unroll
                for (int ni = 0; ni < 4; ni++)
                    mma8(acc[mi][ni], a[mi], b[ni]);
        }
    };

    // ---- 3-stage cp.async pipeline (2 prefetched) ----
    fill(0, 0); asm volatile("cp.async.commit_group;" ::: "memory");
    fill(1, 1); asm volatile("cp.async.commit_group;" ::: "memory");

    int cs = 0, fs = 2;
    for (int kt = 0; kt < NKT; kt++) {
        if (kt < NKT - 1) asm volatile("cp.async.wait_group 1;" ::: "memory");
        else              asm volatile("cp.async.wait_group 0;" ::: "memory");
        __syncthreads();
        if (kt + 2 < NKT) {
            fill(kt + 2, fs);
            asm volatile("cp.async.commit_group;" ::: "memory");
            fs = (fs == STAGES - 1) ? 0 : fs + 1;
        }
        compute(cs);
        cs = (cs == STAGES - 1) ? 0 : cs + 1;
    }

    // ---- epilogue: acc -> smem zbuf -> fused LSTM math -> h_t, c_t ----
    __syncthreads();
    float* z = (float*)smem;    // 128 x 132 floats = 67584 B
    #pragma unroll
    for (int mi = 0; mi < 4; mi++)
        #pragma unroll
        for (int ni = 0; ni < 4; ni++) {
            const int r0  = wm * 64 + mi * 16 + tr;
            const int col = wn * 32 + ni * 8 + tc * 2;
            z[r0 * ZS + col]           = acc[mi][ni][0];
            z[r0 * ZS + col + 1]       = acc[mi][ni][1];
            z[(r0 + 8) * ZS + col]     = acc[mi][ni][2];
            z[(r0 + 8) * ZS + col + 1] = acc[mi][ni][3];
        }
    __syncthreads();

    // outputs: 128 rows x 32 hid = 4096 elems; 16 passes of 256 threads.
    const int j   = tid & 31;
    const int rw  = tid >> 5;           // 0..7
    const int hid = nt * 32 + j;
    const float bfv = bf[hid], biv = bi[hid], bcv = bc[hid], bov = bo[hid];
    float* out_h = out;
    float* out_c = out + (size_t)8192 * 2048;

    #pragma unroll 4
    for (int p = 0; p < 16; p++) {
        const int row = p * 8 + rw;
        const float zf = z[row * ZS + j]      + bfv;
        const float zi = z[row * ZS + 32 + j] + biv;
        const float zc = z[row * ZS + 64 + j] + bcv;
        const float zo = z[row * ZS + 96 + j] + bov;
        const size_t gi = (size_t)(mt * BM + row) * 2048 + hid;
        const float cprev = cp[gi];
        const float ft = 1.0f / (1.0f + __expf(-zf));
        const float it = 1.0f / (1.0f + __expf(-zi));
        const float cb = tanhf(zc);
        const float ot = 1.0f / (1.0f + __expf(-zo));
        const float ct = cprev * ft + it * cb;
        out_h[gi] = ot * tanhf(ct);
        out_c[gi] = ct;
    }
}

extern "C" void kernel_launch(void* const* d_in, const int* in_sizes, int n_in,
                              void* d_out, int out_size) {
    (void)in_sizes; (void)n_in; (void)out_size;
    const float* x  = (const float*)d_in[0];
    const float* hp = (const float*)d_in[1];
    const float* cp = (const float*)d_in[2];
    // d_in[3] = embedding_vec (ignored in vanilla mode)
    const float* Wf = (const float*)d_in[4];
    const float* Wi = (const float*)d_in[5];
    const float* Wc = (const float*)d_in[6];
    const float* Wo = (const float*)d_in[7];
    const float* bf = (const float*)d_in[8];
    const float* bi = (const float*)d_in[9];
    const float* bc = (const float*)d_in[10];
    const float* bo = (const float*)d_in[11];
    float* out = (float*)d_out;

    // 1) pre-round all GEMM operands to tf32 grid (rna) in scratch
    dim3 pgrid(1024, 6);
    prep_kernel<<<pgrid, 256>>>(x, hp, Wf, Wi, Wc, Wo);

    // 2) fused GEMM + LSTM epilogue
    cudaFuncSetAttribute(lstm_fused_kernel,
                         cudaFuncAttributeMaxDynamicSharedMemorySize, SMEM_TOTAL);
    dim3 grid(64, 64);   // x = nt (fastest), y = mt
    lstm_fused_kernel<<<grid, THREADS, SMEM_TOTAL>>>(
        cp, bf, bi, bc, bo, out);
}

// round 16
// speedup vs baseline: 1.4918x; 1.0038x over previous
#include <cuda_runtime.h>
#include <cstdint>
#include <math.h>

// ---------------------------------------------------------------------------
// EmbeddingLSTMCell on GB300 (sm_103a) -- base-target mma.sync path
//   z = [x | h_prev] @ [Wf|Wi|Wc|Wo] + b    (B=8192, K=4096, 4*HID=8192)
//   f,i,o = sigmoid; c~ = tanh; c_t = c_prev*f + i*c~; h_t = o*tanh(c_t)
//
// R16 = R15 resubmitted verbatim (R15 bench died to a container-infra
// failure before measuring): A-side ldmatrix. R14 config (256 thr, 8 warps
// 2m x 4n, warp tile 64x32, 2 CTAs/SM, 3-stage cp.async, pre-rounded tf32
// operands) but A fragments load via ldmatrix.m8n8.x4 from the unchanged
// [m][32k] smem tile (36-float pitch is LDSM conflict-free). B stays
// scalar LDS. Loop issues per k8: 40 -> 28. Bit-identical numerics.
// ---------------------------------------------------------------------------

#define THREADS      256
#define BM           128
#define BK           32
#define NKT          128          // 4096 / 32
#define STAGES       3
#define A_ROW_F      36           // 32 + 4 pad (LDSM rows cover all 32 banks)
#define B_ROW_F      136          // 128 + 8 pad (B frag banks 8*tc+tr distinct)
#define A_BYTES      (BM * A_ROW_F * 4)              // 18432
#define B_OFF        A_BYTES
#define STAGE_BYTES  (A_BYTES + 32 * B_ROW_F * 4)    // 35840
#define SMEM_TOTAL   (STAGES * STAGE_BYTES)          // 107520 (x2 CTAs = 215K)
#define ZS           132          // zbuf row stride; 128*132*4 = 67584 B

#define NF_X   16777216           // 8192*2048
#define NF_W   8388608            // 4096*2048
#define N4_X   (NF_X / 4)
#define N4_W   (NF_W / 4)

// pre-rounded (rna->tf32, stored as fp32 with low 13 bits zero) operands
__device__ float g_xr[NF_X];
__device__ float g_hr[NF_X];
__device__ float g_wfr[NF_W];
__device__ float g_wir[NF_W];
__device__ float g_wcr[NF_W];
__device__ float g_wor[NF_W];

static __device__ __forceinline__ uint32_t smem_u32(const void* p) {
    uint32_t a;
    asm("{ .reg .u64 t; cvta.to.shared.u64 t, %1; cvt.u32.u64 %0, t; }"
        : "=r"(a) : "l"(p));
    return a;
}

static __device__ __forceinline__ uint32_t f2tf(float f) {
    uint32_t r;
    asm("cvt.rna.tf32.f32 %0, %1;" : "=r"(r) : "f"(f));
    return r;
}

static __device__ __forceinline__ void cp16(uint32_t saddr, const void* g) {
    asm volatile("cp.async.cg.shared.global [%0], [%1], 16;"
                 :: "r"(saddr), "l"(g));
}

static __device__ __forceinline__ void ldsm4(uint32_t* d, uint32_t addr) {
    asm volatile(
        "ldmatrix.sync.aligned.m8n8.x4.shared.b16 {%0,%1,%2,%3}, [%4];"
        : "=r"(d[0]), "=r"(d[1]), "=r"(d[2]), "=r"(d[3]) : "r"(addr));
}

static __device__ __forceinline__ void mma8(float* c, const uint32_t* a,
                                            const uint32_t* b) {
    asm volatile(
        "mma.sync.aligned.m16n8k8.row.col.f32.tf32.tf32.f32 "
        "{%0,%1,%2,%3}, {%4,%5,%6,%7}, {%8,%9}, {%0,%1,%2,%3};"
        : "+f"(c[0]), "+f"(c[1]), "+f"(c[2]), "+f"(c[3])
        : "r"(a[0]), "r"(a[1]), "r"(a[2]), "r"(a[3]), "r"(b[0]), "r"(b[1]));
}

// ---- prep: rna-round to tf32 grid, store bit patterns as fp32 ----
__global__ void __launch_bounds__(256)
prep_kernel(const float* __restrict__ x,  const float* __restrict__ hp,
            const float* __restrict__ Wf, const float* __restrict__ Wi,
            const float* __restrict__ Wc, const float* __restrict__ Wo)
{
    const int t = blockIdx.x * blockDim.x + threadIdx.x;
    const int stride = gridDim.x * blockDim.x;
    const float* src; float* dst; int n4;
    switch (blockIdx.y) {
        case 0:  src = x;  dst = g_xr;  n4 = N4_X; break;
        case 1:  src = hp; dst = g_hr;  n4 = N4_X; break;
        case 2:  src = Wf; dst = g_wfr; n4 = N4_W; break;
        case 3:  src = Wi; dst = g_wir; n4 = N4_W; break;
        case 4:  src = Wc; dst = g_wcr; n4 = N4_W; break;
        default: src = Wo; dst = g_wor; n4 = N4_W; break;
    }
    const float4* s4 = (const float4*)src;
    uint4* d4 = (uint4*)dst;
    for (int i = t; i < n4; i += stride) {
        float4 v = s4[i];
        uint4 u;
        u.x = f2tf(v.x); u.y = f2tf(v.y); u.z = f2tf(v.z); u.w = f2tf(v.w);
        d4[i] = u;
    }
}

__global__ void __launch_bounds__(THREADS, 2)
lstm_fused_kernel(const float* __restrict__ cp,
                  const float* __restrict__ bf, const float* __restrict__ bi,
                  const float* __restrict__ bc, const float* __restrict__ bo,
                  float* __restrict__ out)
{
    extern __shared__ char smem[];
    const int tid  = threadIdx.x;
    const int lane = tid & 31;
    const int wid  = tid >> 5;     // 0..7
    const int wm   = wid & 1;      // warp row (M): 2 warps * 64 rows
    const int wn   = wid >> 1;     // warp col (N): 4 warps * 32 cols
    const int tr   = lane >> 2;    // groupID (0..7)
    const int tc   = lane & 3;     // thread-in-group (0..3)
    const int nt   = blockIdx.x;   // 0..63 hid tile (32 hid cols per gate)
    const int mt   = blockIdx.y;   // 0..63 batch tile (128 rows)
    const uint32_t sbase = smem_u32(smem);

    float acc[4][4][4];
    #pragma unroll
    for (int mi = 0; mi < 4; mi++)
        #pragma unroll
        for (int ni = 0; ni < 4; ni++)
            #pragma unroll
            for (int j = 0; j < 4; j++) acc[mi][ni][j] = 0.0f;

    // ---- async stage fill: 2048 16B chunks per stage, 8 per thread ----
    auto fill = [&](int kt, int s) {
        const uint32_t sb = sbase + (uint32_t)s * STAGE_BYTES;
        const float* asrc = (kt < 64) ? g_xr : g_hr;
        const int kb = (kt & 63) * BK;
        #pragma unroll
        for (int i = 0; i < 4; i++) {
            const int q = tid + i * THREADS;    // 0..1023
            const int r = q >> 3, c = q & 7;
            cp16(sb + r * (A_ROW_F * 4) + c * 16,
                 asrc + (size_t)(mt * BM + r) * 2048 + kb + c * 4);
        }
        #pragma unroll
        for (int i = 0; i < 4; i++) {
            const int q = tid + i * THREADS;    // 0..1023
            const int k = q >> 5, ch = q & 31;
            const int g = ch >> 3, j = (ch & 7) * 4;
            const float* w = (g == 0) ? g_wfr : (g == 1) ? g_wir
                           : (g == 2) ? g_wcr : g_wor;
            cp16(sb + B_OFF + k * (B_ROW_F * 4) + g * 128 + j * 4,
                 w + (size_t)(kt * BK + k) * 2048 + nt * 32 + j);
        }
    };

    // ---- A-side ldmatrix addressing ----
    // frag mi covers rows wm*64+mi*16..+15, k ks*8..+7 as 4 8x8-b16 matrices:
    //   q0: rows +0..7,  k +0..3   -> a0
    //   q1: rows +8..15, k +0..3   -> a1
    //   q2: rows +0..7,  k +4..7   -> a2
    //   q3: rows +8..15, k +4..7   -> a3
    const int mq = lane >> 3, mr = lane & 7;
    const uint32_t aoff = ((wm * 64 + (mq & 1) * 8 + mr) * A_ROW_F
                           + (mq >> 1) * 4) * 4;

    // ---- compute one K-stage: 4 k8 x (4 LDSM + 8 LDS + 16 HMMA) ----
    auto compute = [&](int s) {
        const uint32_t sb = sbase + (uint32_t)s * STAGE_BYTES;
        const float* Bs = (const float*)(smem + (size_t)s * STAGE_BYTES + B_OFF);
        #pragma unroll
        for (int ks = 0; ks < 4; ks++) {
            uint32_t a[4][4], b[4][2];
            #pragma unroll
            for (int mi = 0; mi < 4; mi++)
                ldsm4(a[mi], sb + aoff + mi * 16 * A_ROW_F * 4 + ks * 32);
            #pragma unroll
            for (int ni = 0; ni < 4; ni++) {
                const float* bp = Bs + (ks * 8 + tc) * B_ROW_F
                                     + wn * 32 + ni * 8 + tr;
                b[ni][0] = __float_as_uint(bp[0]);
                b[ni][1] = __float_as_uint(bp[4 * B_ROW_F]);
            }
            #pragma unroll
            for (int mi = 0; mi < 4; mi++)
                #pragma unroll
                for (int ni = 0; ni < 4; ni++)
                    mma8(acc[mi][ni], a[mi], b[ni]);
        }
    };

    // ---- 3-stage cp.async pipeline (2 prefetched) ----
    fill(0, 0); asm volatile("cp.async.commit_group;" ::: "memory");
    fill(1, 1); asm volatile("cp.async.commit_group;" ::: "memory");

    int cs = 0, fs = 2;
    for (int kt = 0; kt < NKT; kt++) {
        if (kt < NKT - 1) asm volatile("cp.async.wait_group 1;" ::: "memory");
        else              asm volatile("cp.async.wait_group 0;" ::: "memory");
        __syncthreads();
        if (kt + 2 < NKT) {
            fill(kt + 2, fs);
            asm volatile("cp.async.commit_group;" ::: "memory");
            fs = (fs == STAGES - 1) ? 0 : fs + 1;
        }
        compute(cs);
        cs = (cs == STAGES - 1) ? 0 : cs + 1;
    }

    // ---- epilogue: acc -> smem zbuf -> fused LSTM math -> h_t, c_t ----
    __syncthreads();
    float* z = (float*)smem;    // 128 x 132 floats = 67584 B
    #pragma unroll
    for (int mi = 0; mi < 4; mi++)
        #pragma unroll
        for (int ni = 0; ni < 4; ni++) {
            const int r0  = wm * 64 + mi * 16 + tr;
            const int col = wn * 32 + ni * 8 + tc * 2;
            z[r0 * ZS + col]           = acc[mi][ni][0];
            z[r0 * ZS + col + 1]       = acc[mi][ni][1];
            z[(r0 + 8) * ZS + col]     = acc[mi][ni][2];
            z[(r0 + 8) * ZS + col + 1] = acc[mi][ni][3];
        }
    __syncthreads();

    // outputs: 128 rows x 32 hid = 4096 elems; 16 passes of 256 threads.
    const int j   = tid & 31;
    const int rw  = tid >> 5;           // 0..7
    const int hid = nt * 32 + j;
    const float bfv = bf[hid], biv = bi[hid], bcv = bc[hid], bov = bo[hid];
    float* out_h = out;
    float* out_c = out + (size_t)8192 * 2048;

    #pragma unroll 4
    for (int p = 0; p < 16; p++) {
        const int row = p * 8 + rw;
        const float zf = z[row * ZS + j]      + bfv;
        const float zi = z[row * ZS + 32 + j] + biv;
        const float zc = z[row * ZS + 64 + j] + bcv;
        const float zo = z[row * ZS + 96 + j] + bov;
        const size_t gi = (size_t)(mt * BM + row) * 2048 + hid;
        const float cprev = cp[gi];
        const float ft = 1.0f / (1.0f + __expf(-zf));
        const float it = 1.0f / (1.0f + __expf(-zi));
        const float cb = tanhf(zc);
        const float ot = 1.0f / (1.0f + __expf(-zo));
        const float ct = cprev * ft + it * cb;
        out_h[gi] = ot * tanhf(ct);
        out_c[gi] = ct;
    }
}

extern "C" void kernel_launch(void* const* d_in, const int* in_sizes, int n_in,
                              void* d_out, int out_size) {
    (void)in_sizes; (void)n_in; (void)out_size;
    const float* x  = (const float*)d_in[0];
    const float* hp = (const float*)d_in[1];
    const float* cp = (const float*)d_in[2];
    // d_in[3] = embedding_vec (ignored in vanilla mode)
    const float* Wf = (const float*)d_in[4];
    const float* Wi = (const float*)d_in[5];
    const float* Wc = (const float*)d_in[6];
    const float* Wo = (const float*)d_in[7];
    const float* bf = (const float*)d_in[8];
    const float* bi = (const float*)d_in[9];
    const float* bc = (const float*)d_in[10];
    const float* bo = (const float*)d_in[11];
    float* out = (float*)d_out;

    // 1) pre-round all GEMM operands to tf32 grid (rna) in scratch
    dim3 pgrid(1024, 6);
    prep_kernel<<<pgrid, 256>>>(x, hp, Wf, Wi, Wc, Wo);

    // 2) fused GEMM + LSTM epilogue
    cudaFuncSetAttribute(lstm_fused_kernel,
                         cudaFuncAttributeMaxDynamicSharedMemorySize, SMEM_TOTAL);
    dim3 grid(64, 64);   // x = nt (fastest), y = mt
    lstm_fused_kernel<<<grid, THREADS, SMEM_TOTAL>>>(
        cp, bf, bi, bc, bo, out);
}